// round 1
// baseline (speedup 1.0000x reference)
#include <cuda_runtime.h>
#include <math.h>

// Problem constants
#define LSEQ 4096
#define DMODEL 1024

// Scratch (static __device__ arrays -- no runtime allocation)
__device__ float g_Q[LSEQ * DMODEL];
__device__ float g_K[LSEQ * DMODEL];
__device__ float g_V[LSEQ * DMODEL];
__device__ float g_S[(size_t)LSEQ * LSEQ];   // scores, then probabilities in-place

#define BM 128
#define BN 128
#define BK 16
#define NTHREADS 256

// ---------------------------------------------------------------------------
// Kernel 1: fused QKV projection. blockIdx.z selects which of Q/K/V.
// C[L, D] = A[L, D] @ W[D, D] + b
// ---------------------------------------------------------------------------
__global__ __launch_bounds__(NTHREADS, 2)
void proj_kernel(const float* __restrict__ x, const float* __restrict__ z,
                 const float* __restrict__ Wq, const float* __restrict__ bq,
                 const float* __restrict__ Wk, const float* __restrict__ bk,
                 const float* __restrict__ Wv, const float* __restrict__ bv)
{
    const float* A; const float* W; const float* bias; float* C;
    int which = blockIdx.z;
    if (which == 0)      { A = x; W = Wq; bias = bq; C = g_Q; }
    else if (which == 1) { A = z; W = Wk; bias = bk; C = g_K; }
    else                 { A = z; W = Wv; bias = bv; C = g_V; }

    __shared__ float As[BK][BM + 4];   // As[k][m], padded vs bank conflicts
    __shared__ float Bs[BK][BN];       // Bs[k][n]

    const int tid = threadIdx.x;
    const int tx = tid & 15;
    const int ty = tid >> 4;
    const int m0 = blockIdx.y * BM;
    const int n0 = blockIdx.x * BN;

    float acc[8][8];
#pragma unroll
    for (int i = 0; i < 8; i++)
#pragma unroll
        for (int j = 0; j < 8; j++) acc[i][j] = 0.0f;

    for (int k0 = 0; k0 < DMODEL; k0 += BK) {
        // Load A tile (transposed into As[k][m])
#pragma unroll
        for (int i = 0; i < 2; i++) {
            int idx = tid * 2 + i;                 // 0..511
            int m   = idx >> 2;                    // 0..127
            int kc  = (idx & 3) << 2;              // 0,4,8,12
            float4 v = *(const float4*)(A + (size_t)(m0 + m) * DMODEL + k0 + kc);
            As[kc + 0][m] = v.x; As[kc + 1][m] = v.y;
            As[kc + 2][m] = v.z; As[kc + 3][m] = v.w;
        }
        // Load W tile (natural Bs[k][n])
#pragma unroll
        for (int i = 0; i < 2; i++) {
            int idx = tid * 2 + i;
            int k   = idx >> 5;                    // 0..15
            int n   = (idx & 31) << 2;             // 0..124
            *(float4*)&Bs[k][n] =
                *(const float4*)(W + (size_t)(k0 + k) * DMODEL + n0 + n);
        }
        __syncthreads();

#pragma unroll
        for (int kk = 0; kk < BK; kk++) {
            float a[8], b[8];
            *(float4*)&a[0] = *(const float4*)&As[kk][ty * 8 + 0];
            *(float4*)&a[4] = *(const float4*)&As[kk][ty * 8 + 4];
            *(float4*)&b[0] = *(const float4*)&Bs[kk][tx * 4];
            *(float4*)&b[4] = *(const float4*)&Bs[kk][64 + tx * 4];
#pragma unroll
            for (int i = 0; i < 8; i++)
#pragma unroll
                for (int j = 0; j < 8; j++)
                    acc[i][j] = fmaf(a[i], b[j], acc[i][j]);
        }
        __syncthreads();
    }

    // Epilogue with bias
    float bv0[8];
#pragma unroll
    for (int j = 0; j < 4; j++) {
        bv0[j]     = bias[n0 + tx * 4 + j];
        bv0[4 + j] = bias[n0 + 64 + tx * 4 + j];
    }
#pragma unroll
    for (int i = 0; i < 8; i++) {
        int m = m0 + ty * 8 + i;
        float4 r0, r1;
        r0.x = acc[i][0] + bv0[0]; r0.y = acc[i][1] + bv0[1];
        r0.z = acc[i][2] + bv0[2]; r0.w = acc[i][3] + bv0[3];
        r1.x = acc[i][4] + bv0[4]; r1.y = acc[i][5] + bv0[5];
        r1.z = acc[i][6] + bv0[6]; r1.w = acc[i][7] + bv0[7];
        *(float4*)(C + (size_t)m * DMODEL + n0 + tx * 4)      = r0;
        *(float4*)(C + (size_t)m * DMODEL + n0 + 64 + tx * 4) = r1;
    }
}

// ---------------------------------------------------------------------------
// Kernel 2: S = Q @ K^T (raw scores, no scale). Skips fully-masked blocks:
// row i only attends j >= i, so block (rb, cb) with cb*BN + BN <= rb*BM is dead.
// ---------------------------------------------------------------------------
__global__ __launch_bounds__(NTHREADS, 2)
void qk_kernel()
{
    const int m0 = blockIdx.y * BM;
    const int n0 = blockIdx.x * BN;
    if (n0 + BN <= m0) return;   // entirely strictly-lower -> masked

    __shared__ float As[BK][BM + 4];   // Q tile transposed
    __shared__ float Bs[BK][BN + 4];   // K tile transposed (K is [n][k] row-major)

    const int tid = threadIdx.x;
    const int tx = tid & 15;
    const int ty = tid >> 4;

    float acc[8][8];
#pragma unroll
    for (int i = 0; i < 8; i++)
#pragma unroll
        for (int j = 0; j < 8; j++) acc[i][j] = 0.0f;

    for (int k0 = 0; k0 < DMODEL; k0 += BK) {
#pragma unroll
        for (int i = 0; i < 2; i++) {
            int idx = tid * 2 + i;
            int m   = idx >> 2;
            int kc  = (idx & 3) << 2;
            float4 v = *(const float4*)(g_Q + (size_t)(m0 + m) * DMODEL + k0 + kc);
            As[kc + 0][m] = v.x; As[kc + 1][m] = v.y;
            As[kc + 2][m] = v.z; As[kc + 3][m] = v.w;
        }
#pragma unroll
        for (int i = 0; i < 2; i++) {
            int idx = tid * 2 + i;
            int n   = idx >> 2;
            int kc  = (idx & 3) << 2;
            float4 v = *(const float4*)(g_K + (size_t)(n0 + n) * DMODEL + k0 + kc);
            Bs[kc + 0][n] = v.x; Bs[kc + 1][n] = v.y;
            Bs[kc + 2][n] = v.z; Bs[kc + 3][n] = v.w;
        }
        __syncthreads();

#pragma unroll
        for (int kk = 0; kk < BK; kk++) {
            float a[8], b[8];
            *(float4*)&a[0] = *(const float4*)&As[kk][ty * 8 + 0];
            *(float4*)&a[4] = *(const float4*)&As[kk][ty * 8 + 4];
            *(float4*)&b[0] = *(const float4*)&Bs[kk][tx * 4];
            *(float4*)&b[4] = *(const float4*)&Bs[kk][64 + tx * 4];
#pragma unroll
            for (int i = 0; i < 8; i++)
#pragma unroll
                for (int j = 0; j < 8; j++)
                    acc[i][j] = fmaf(a[i], b[j], acc[i][j]);
        }
        __syncthreads();
    }

#pragma unroll
    for (int i = 0; i < 8; i++) {
        int m = m0 + ty * 8 + i;
        float4 r0, r1;
        r0.x = acc[i][0]; r0.y = acc[i][1]; r0.z = acc[i][2]; r0.w = acc[i][3];
        r1.x = acc[i][4]; r1.y = acc[i][5]; r1.z = acc[i][6]; r1.w = acc[i][7];
        *(float4*)(g_S + (size_t)m * LSEQ + n0 + tx * 4)      = r0;
        *(float4*)(g_S + (size_t)m * LSEQ + n0 + 64 + tx * 4) = r1;
    }
}

// ---------------------------------------------------------------------------
// Kernel 3: in-place masked row softmax of S/sqrt(D_ATTN).
// Row i: softmax over j in [i, L); zeros written for j < i.
// ---------------------------------------------------------------------------
__global__ void softmax_kernel()
{
    const int i = blockIdx.x;
    float* row = g_S + (size_t)i * LSEQ;
    const int tid = threadIdx.x;
    const float sc = 0.03125f;   // 1/sqrt(1024)
    __shared__ float red[8];
    __shared__ float bcast;

    // Pass 1: max over valid region
    float m = -INFINITY;
    for (int j = i + tid; j < LSEQ; j += NTHREADS) m = fmaxf(m, row[j]);
#pragma unroll
    for (int o = 16; o; o >>= 1) m = fmaxf(m, __shfl_xor_sync(0xFFFFFFFFu, m, o));
    if ((tid & 31) == 0) red[tid >> 5] = m;
    __syncthreads();
    if (tid < 32) {
        float v = (tid < 8) ? red[tid] : -INFINITY;
#pragma unroll
        for (int o = 4; o; o >>= 1) v = fmaxf(v, __shfl_xor_sync(0xFFFFFFFFu, v, o));
        if (tid == 0) bcast = v;
    }
    __syncthreads();
    m = bcast;
    __syncthreads();

    // Pass 2: sum of exp
    float s = 0.0f;
    for (int j = i + tid; j < LSEQ; j += NTHREADS) s += expf((row[j] - m) * sc);
#pragma unroll
    for (int o = 16; o; o >>= 1) s += __shfl_xor_sync(0xFFFFFFFFu, s, o);
    if ((tid & 31) == 0) red[tid >> 5] = s;
    __syncthreads();
    if (tid < 32) {
        float v = (tid < 8) ? red[tid] : 0.0f;
#pragma unroll
        for (int o = 4; o; o >>= 1) v += __shfl_xor_sync(0xFFFFFFFFu, v, o);
        if (tid == 0) bcast = v;
    }
    __syncthreads();
    const float inv = 1.0f / bcast;

    // Pass 3: write full row (zeros in masked prefix so PV can run dense tiles)
    for (int j = tid; j < LSEQ; j += NTHREADS) {
        float v = (j < i) ? 0.0f : expf((row[j] - m) * sc) * inv;
        row[j] = v;
    }
}

// ---------------------------------------------------------------------------
// Kernel 4: O = P @ V. For output row-block starting at m0, all probability
// mass is at j >= m0, so the k-loop starts at m0 (triangle exploit).
// ---------------------------------------------------------------------------
__global__ __launch_bounds__(NTHREADS, 2)
void pv_kernel(float* __restrict__ out)
{
    const int m0 = blockIdx.y * BM;
    const int n0 = blockIdx.x * BN;

    __shared__ float As[BK][BM + 4];   // P tile transposed
    __shared__ float Bs[BK][BN];       // V tile natural

    const int tid = threadIdx.x;
    const int tx = tid & 15;
    const int ty = tid >> 4;

    float acc[8][8];
#pragma unroll
    for (int i = 0; i < 8; i++)
#pragma unroll
        for (int j = 0; j < 8; j++) acc[i][j] = 0.0f;

    for (int k0 = m0; k0 < LSEQ; k0 += BK) {
#pragma unroll
        for (int i = 0; i < 2; i++) {
            int idx = tid * 2 + i;
            int m   = idx >> 2;
            int kc  = (idx & 3) << 2;
            float4 v = *(const float4*)(g_S + (size_t)(m0 + m) * LSEQ + k0 + kc);
            As[kc + 0][m] = v.x; As[kc + 1][m] = v.y;
            As[kc + 2][m] = v.z; As[kc + 3][m] = v.w;
        }
#pragma unroll
        for (int i = 0; i < 2; i++) {
            int idx = tid * 2 + i;
            int k   = idx >> 5;
            int n   = (idx & 31) << 2;
            *(float4*)&Bs[k][n] =
                *(const float4*)(g_V + (size_t)(k0 + k) * DMODEL + n0 + n);
        }
        __syncthreads();

#pragma unroll
        for (int kk = 0; kk < BK; kk++) {
            float a[8], b[8];
            *(float4*)&a[0] = *(const float4*)&As[kk][ty * 8 + 0];
            *(float4*)&a[4] = *(const float4*)&As[kk][ty * 8 + 4];
            *(float4*)&b[0] = *(const float4*)&Bs[kk][tx * 4];
            *(float4*)&b[4] = *(const float4*)&Bs[kk][64 + tx * 4];
#pragma unroll
            for (int i = 0; i < 8; i++)
#pragma unroll
                for (int j = 0; j < 8; j++)
                    acc[i][j] = fmaf(a[i], b[j], acc[i][j]);
        }
        __syncthreads();
    }

#pragma unroll
    for (int i = 0; i < 8; i++) {
        int m = m0 + ty * 8 + i;
        float4 r0, r1;
        r0.x = acc[i][0]; r0.y = acc[i][1]; r0.z = acc[i][2]; r0.w = acc[i][3];
        r1.x = acc[i][4]; r1.y = acc[i][5]; r1.z = acc[i][6]; r1.w = acc[i][7];
        *(float4*)(out + (size_t)m * DMODEL + n0 + tx * 4)      = r0;
        *(float4*)(out + (size_t)m * DMODEL + n0 + 64 + tx * 4) = r1;
    }
}

// ---------------------------------------------------------------------------
extern "C" void kernel_launch(void* const* d_in, const int* in_sizes, int n_in,
                              void* d_out, int out_size)
{
    const float* x  = (const float*)d_in[0];
    const float* z  = (const float*)d_in[1];
    const float* Wq = (const float*)d_in[2];
    const float* bq = (const float*)d_in[3];
    const float* Wk = (const float*)d_in[4];
    const float* bk = (const float*)d_in[5];
    const float* Wv = (const float*)d_in[6];
    const float* bv = (const float*)d_in[7];
    float* out = (float*)d_out;

    dim3 blk(NTHREADS);
    proj_kernel<<<dim3(DMODEL / BN, LSEQ / BM, 3), blk>>>(x, z, Wq, bq, Wk, bk, Wv, bv);
    qk_kernel<<<dim3(LSEQ / BN, LSEQ / BM), blk>>>();
    softmax_kernel<<<dim3(LSEQ), blk>>>();
    pv_kernel<<<dim3(DMODEL / BN, LSEQ / BM), blk>>>(out);
}

// round 2
// speedup vs baseline: 1.0001x; 1.0001x over previous
#include <cuda_runtime.h>
#include <math.h>

// Problem constants
#define LSEQ 4096
#define DMODEL 1024

// Scratch (static __device__ arrays -- no runtime allocation)
__device__ float g_Q[LSEQ * DMODEL];
__device__ float g_K[LSEQ * DMODEL];
__device__ float g_V[LSEQ * DMODEL];
__device__ float g_S[(size_t)LSEQ * LSEQ];   // scores, then probabilities in-place

#define BM 128
#define BN 128
#define BK 16
#define NTHREADS 256

// ---------------------------------------------------------------------------
// Kernel 1: fused QKV projection. blockIdx.z selects which of Q/K/V.
// C[L, D] = A[L, D] @ W[D, D] + b
// ---------------------------------------------------------------------------
__global__ __launch_bounds__(NTHREADS, 2)
void proj_kernel(const float* __restrict__ x, const float* __restrict__ z,
                 const float* __restrict__ Wq, const float* __restrict__ bq,
                 const float* __restrict__ Wk, const float* __restrict__ bk,
                 const float* __restrict__ Wv, const float* __restrict__ bv)
{
    const float* A; const float* W; const float* bias; float* C;
    int which = blockIdx.z;
    if (which == 0)      { A = x; W = Wq; bias = bq; C = g_Q; }
    else if (which == 1) { A = z; W = Wk; bias = bk; C = g_K; }
    else                 { A = z; W = Wv; bias = bv; C = g_V; }

    __shared__ float As[BK][BM + 4];   // As[k][m], padded vs bank conflicts
    __shared__ float Bs[BK][BN];       // Bs[k][n]

    const int tid = threadIdx.x;
    const int tx = tid & 15;
    const int ty = tid >> 4;
    const int m0 = blockIdx.y * BM;
    const int n0 = blockIdx.x * BN;

    float acc[8][8];
#pragma unroll
    for (int i = 0; i < 8; i++)
#pragma unroll
        for (int j = 0; j < 8; j++) acc[i][j] = 0.0f;

    for (int k0 = 0; k0 < DMODEL; k0 += BK) {
        // Load A tile (transposed into As[k][m])
#pragma unroll
        for (int i = 0; i < 2; i++) {
            int idx = tid * 2 + i;                 // 0..511
            int m   = idx >> 2;                    // 0..127
            int kc  = (idx & 3) << 2;              // 0,4,8,12
            float4 v = *(const float4*)(A + (size_t)(m0 + m) * DMODEL + k0 + kc);
            As[kc + 0][m] = v.x; As[kc + 1][m] = v.y;
            As[kc + 2][m] = v.z; As[kc + 3][m] = v.w;
        }
        // Load W tile (natural Bs[k][n])
#pragma unroll
        for (int i = 0; i < 2; i++) {
            int idx = tid * 2 + i;
            int k   = idx >> 5;                    // 0..15
            int n   = (idx & 31) << 2;             // 0..124
            *(float4*)&Bs[k][n] =
                *(const float4*)(W + (size_t)(k0 + k) * DMODEL + n0 + n);
        }
        __syncthreads();

#pragma unroll
        for (int kk = 0; kk < BK; kk++) {
            float a[8], b[8];
            *(float4*)&a[0] = *(const float4*)&As[kk][ty * 8 + 0];
            *(float4*)&a[4] = *(const float4*)&As[kk][ty * 8 + 4];
            *(float4*)&b[0] = *(const float4*)&Bs[kk][tx * 4];
            *(float4*)&b[4] = *(const float4*)&Bs[kk][64 + tx * 4];
#pragma unroll
            for (int i = 0; i < 8; i++)
#pragma unroll
                for (int j = 0; j < 8; j++)
                    acc[i][j] = fmaf(a[i], b[j], acc[i][j]);
        }
        __syncthreads();
    }

    // Epilogue with bias
    float bv0[8];
#pragma unroll
    for (int j = 0; j < 4; j++) {
        bv0[j]     = bias[n0 + tx * 4 + j];
        bv0[4 + j] = bias[n0 + 64 + tx * 4 + j];
    }
#pragma unroll
    for (int i = 0; i < 8; i++) {
        int m = m0 + ty * 8 + i;
        float4 r0, r1;
        r0.x = acc[i][0] + bv0[0]; r0.y = acc[i][1] + bv0[1];
        r0.z = acc[i][2] + bv0[2]; r0.w = acc[i][3] + bv0[3];
        r1.x = acc[i][4] + bv0[4]; r1.y = acc[i][5] + bv0[5];
        r1.z = acc[i][6] + bv0[6]; r1.w = acc[i][7] + bv0[7];
        *(float4*)(C + (size_t)m * DMODEL + n0 + tx * 4)      = r0;
        *(float4*)(C + (size_t)m * DMODEL + n0 + 64 + tx * 4) = r1;
    }
}

// ---------------------------------------------------------------------------
// Kernel 2: S = Q @ K^T (raw scores, no scale). Skips fully-masked blocks:
// row i only attends j >= i, so block (rb, cb) with cb*BN + BN <= rb*BM is dead.
// ---------------------------------------------------------------------------
__global__ __launch_bounds__(NTHREADS, 2)
void qk_kernel()
{
    const int m0 = blockIdx.y * BM;
    const int n0 = blockIdx.x * BN;
    if (n0 + BN <= m0) return;   // entirely strictly-lower -> masked

    __shared__ float As[BK][BM + 4];   // Q tile transposed
    __shared__ float Bs[BK][BN + 4];   // K tile transposed (K is [n][k] row-major)

    const int tid = threadIdx.x;
    const int tx = tid & 15;
    const int ty = tid >> 4;

    float acc[8][8];
#pragma unroll
    for (int i = 0; i < 8; i++)
#pragma unroll
        for (int j = 0; j < 8; j++) acc[i][j] = 0.0f;

    for (int k0 = 0; k0 < DMODEL; k0 += BK) {
#pragma unroll
        for (int i = 0; i < 2; i++) {
            int idx = tid * 2 + i;
            int m   = idx >> 2;
            int kc  = (idx & 3) << 2;
            float4 v = *(const float4*)(g_Q + (size_t)(m0 + m) * DMODEL + k0 + kc);
            As[kc + 0][m] = v.x; As[kc + 1][m] = v.y;
            As[kc + 2][m] = v.z; As[kc + 3][m] = v.w;
        }
#pragma unroll
        for (int i = 0; i < 2; i++) {
            int idx = tid * 2 + i;
            int n   = idx >> 2;
            int kc  = (idx & 3) << 2;
            float4 v = *(const float4*)(g_K + (size_t)(n0 + n) * DMODEL + k0 + kc);
            Bs[kc + 0][n] = v.x; Bs[kc + 1][n] = v.y;
            Bs[kc + 2][n] = v.z; Bs[kc + 3][n] = v.w;
        }
        __syncthreads();

#pragma unroll
        for (int kk = 0; kk < BK; kk++) {
            float a[8], b[8];
            *(float4*)&a[0] = *(const float4*)&As[kk][ty * 8 + 0];
            *(float4*)&a[4] = *(const float4*)&As[kk][ty * 8 + 4];
            *(float4*)&b[0] = *(const float4*)&Bs[kk][tx * 4];
            *(float4*)&b[4] = *(const float4*)&Bs[kk][64 + tx * 4];
#pragma unroll
            for (int i = 0; i < 8; i++)
#pragma unroll
                for (int j = 0; j < 8; j++)
                    acc[i][j] = fmaf(a[i], b[j], acc[i][j]);
        }
        __syncthreads();
    }

#pragma unroll
    for (int i = 0; i < 8; i++) {
        int m = m0 + ty * 8 + i;
        float4 r0, r1;
        r0.x = acc[i][0]; r0.y = acc[i][1]; r0.z = acc[i][2]; r0.w = acc[i][3];
        r1.x = acc[i][4]; r1.y = acc[i][5]; r1.z = acc[i][6]; r1.w = acc[i][7];
        *(float4*)(g_S + (size_t)m * LSEQ + n0 + tx * 4)      = r0;
        *(float4*)(g_S + (size_t)m * LSEQ + n0 + 64 + tx * 4) = r1;
    }
}

// ---------------------------------------------------------------------------
// Kernel 3: in-place masked row softmax of S/sqrt(D_ATTN).
// Row i: softmax over j in [i, L); zeros written for j < i.
// ---------------------------------------------------------------------------
__global__ void softmax_kernel()
{
    const int i = blockIdx.x;
    float* row = g_S + (size_t)i * LSEQ;
    const int tid = threadIdx.x;
    const float sc = 0.03125f;   // 1/sqrt(1024)
    __shared__ float red[8];
    __shared__ float bcast;

    // Pass 1: max over valid region
    float m = -INFINITY;
    for (int j = i + tid; j < LSEQ; j += NTHREADS) m = fmaxf(m, row[j]);
#pragma unroll
    for (int o = 16; o; o >>= 1) m = fmaxf(m, __shfl_xor_sync(0xFFFFFFFFu, m, o));
    if ((tid & 31) == 0) red[tid >> 5] = m;
    __syncthreads();
    if (tid < 32) {
        float v = (tid < 8) ? red[tid] : -INFINITY;
#pragma unroll
        for (int o = 4; o; o >>= 1) v = fmaxf(v, __shfl_xor_sync(0xFFFFFFFFu, v, o));
        if (tid == 0) bcast = v;
    }
    __syncthreads();
    m = bcast;
    __syncthreads();

    // Pass 2: sum of exp
    float s = 0.0f;
    for (int j = i + tid; j < LSEQ; j += NTHREADS) s += expf((row[j] - m) * sc);
#pragma unroll
    for (int o = 16; o; o >>= 1) s += __shfl_xor_sync(0xFFFFFFFFu, s, o);
    if ((tid & 31) == 0) red[tid >> 5] = s;
    __syncthreads();
    if (tid < 32) {
        float v = (tid < 8) ? red[tid] : 0.0f;
#pragma unroll
        for (int o = 4; o; o >>= 1) v += __shfl_xor_sync(0xFFFFFFFFu, v, o);
        if (tid == 0) bcast = v;
    }
    __syncthreads();
    const float inv = 1.0f / bcast;

    // Pass 3: write full row (zeros in masked prefix so PV can run dense tiles)
    for (int j = tid; j < LSEQ; j += NTHREADS) {
        float v = (j < i) ? 0.0f : expf((row[j] - m) * sc) * inv;
        row[j] = v;
    }
}

// ---------------------------------------------------------------------------
// Kernel 4: O = P @ V. For output row-block starting at m0, all probability
// mass is at j >= m0, so the k-loop starts at m0 (triangle exploit).
// ---------------------------------------------------------------------------
__global__ __launch_bounds__(NTHREADS, 2)
void pv_kernel(float* __restrict__ out)
{
    const int m0 = blockIdx.y * BM;
    const int n0 = blockIdx.x * BN;

    __shared__ float As[BK][BM + 4];   // P tile transposed
    __shared__ float Bs[BK][BN];       // V tile natural

    const int tid = threadIdx.x;
    const int tx = tid & 15;
    const int ty = tid >> 4;

    float acc[8][8];
#pragma unroll
    for (int i = 0; i < 8; i++)
#pragma unroll
        for (int j = 0; j < 8; j++) acc[i][j] = 0.0f;

    for (int k0 = m0; k0 < LSEQ; k0 += BK) {
#pragma unroll
        for (int i = 0; i < 2; i++) {
            int idx = tid * 2 + i;
            int m   = idx >> 2;
            int kc  = (idx & 3) << 2;
            float4 v = *(const float4*)(g_S + (size_t)(m0 + m) * LSEQ + k0 + kc);
            As[kc + 0][m] = v.x; As[kc + 1][m] = v.y;
            As[kc + 2][m] = v.z; As[kc + 3][m] = v.w;
        }
#pragma unroll
        for (int i = 0; i < 2; i++) {
            int idx = tid * 2 + i;
            int k   = idx >> 5;
            int n   = (idx & 31) << 2;
            *(float4*)&Bs[k][n] =
                *(const float4*)(g_V + (size_t)(k0 + k) * DMODEL + n0 + n);
        }
        __syncthreads();

#pragma unroll
        for (int kk = 0; kk < BK; kk++) {
            float a[8], b[8];
            *(float4*)&a[0] = *(const float4*)&As[kk][ty * 8 + 0];
            *(float4*)&a[4] = *(const float4*)&As[kk][ty * 8 + 4];
            *(float4*)&b[0] = *(const float4*)&Bs[kk][tx * 4];
            *(float4*)&b[4] = *(const float4*)&Bs[kk][64 + tx * 4];
#pragma unroll
            for (int i = 0; i < 8; i++)
#pragma unroll
                for (int j = 0; j < 8; j++)
                    acc[i][j] = fmaf(a[i], b[j], acc[i][j]);
        }
        __syncthreads();
    }

#pragma unroll
    for (int i = 0; i < 8; i++) {
        int m = m0 + ty * 8 + i;
        float4 r0, r1;
        r0.x = acc[i][0]; r0.y = acc[i][1]; r0.z = acc[i][2]; r0.w = acc[i][3];
        r1.x = acc[i][4]; r1.y = acc[i][5]; r1.z = acc[i][6]; r1.w = acc[i][7];
        *(float4*)(out + (size_t)m * DMODEL + n0 + tx * 4)      = r0;
        *(float4*)(out + (size_t)m * DMODEL + n0 + 64 + tx * 4) = r1;
    }
}

// ---------------------------------------------------------------------------
extern "C" void kernel_launch(void* const* d_in, const int* in_sizes, int n_in,
                              void* d_out, int out_size)
{
    const float* x  = (const float*)d_in[0];
    const float* z  = (const float*)d_in[1];
    const float* Wq = (const float*)d_in[2];
    const float* bq = (const float*)d_in[3];
    const float* Wk = (const float*)d_in[4];
    const float* bk = (const float*)d_in[5];
    const float* Wv = (const float*)d_in[6];
    const float* bv = (const float*)d_in[7];
    float* out = (float*)d_out;

    dim3 blk(NTHREADS);
    proj_kernel<<<dim3(DMODEL / BN, LSEQ / BM, 3), blk>>>(x, z, Wq, bq, Wk, bk, Wv, bv);
    qk_kernel<<<dim3(LSEQ / BN, LSEQ / BM), blk>>>();
    softmax_kernel<<<dim3(LSEQ), blk>>>();
    pv_kernel<<<dim3(DMODEL / BN, LSEQ / BM), blk>>>(out);
}

// round 6
// speedup vs baseline: 3.1810x; 3.1808x over previous
#include <cuda_runtime.h>
#include <cuda_bf16.h>
#include <math.h>
#include <stdint.h>

#define LSEQ   4096
#define DMODEL 1024
typedef __nv_bfloat16 bf16;

// ---------------- static device scratch ------------------------------------
__device__ bf16 g_x0[LSEQ * DMODEL], g_x1[LSEQ * DMODEL];
__device__ bf16 g_z0[LSEQ * DMODEL], g_z1[LSEQ * DMODEL];
__device__ bf16 g_Wq0[DMODEL * DMODEL], g_Wq1[DMODEL * DMODEL];
__device__ bf16 g_Wk0[DMODEL * DMODEL], g_Wk1[DMODEL * DMODEL];
__device__ bf16 g_Wv0[DMODEL * DMODEL], g_Wv1[DMODEL * DMODEL];
__device__ bf16 g_Q0[LSEQ * DMODEL], g_Q1[LSEQ * DMODEL];
__device__ bf16 g_K0[LSEQ * DMODEL], g_K1[LSEQ * DMODEL];
__device__ bf16 g_VT0[DMODEL * LSEQ], g_VT1[DMODEL * LSEQ];
__device__ float g_S[(size_t)LSEQ * LSEQ];
__device__ bf16 g_P0[(size_t)LSEQ * LSEQ], g_P1[(size_t)LSEQ * LSEQ];

// ---------------- helpers ---------------------------------------------------
__device__ __forceinline__ uint32_t s2u(const void* p) {
    uint32_t a;
    asm("{ .reg .u64 t; cvta.to.shared.u64 t, %1; cvt.u32.u64 %0, t; }" : "=r"(a) : "l"(p));
    return a;
}
__device__ __forceinline__ uint32_t pk(bf16 a, bf16 b) {
    return (uint32_t)__bfloat16_as_ushort(a) | ((uint32_t)__bfloat16_as_ushort(b) << 16);
}
__device__ __forceinline__ void split2(float v, bf16& h, bf16& l) {
    h = __float2bfloat16(v);
    l = __float2bfloat16(v - __bfloat162float(h));
}
__device__ __forceinline__ void cp16(uint32_t s, const void* g) {
    asm volatile("cp.async.cg.shared.global [%0], [%1], 16;" :: "r"(s), "l"(g));
}
__device__ __forceinline__ void cp_commit() { asm volatile("cp.async.commit_group;"); }
template <int N> __device__ __forceinline__ void cp_wait() {
    asm volatile("cp.async.wait_group %0;" :: "n"(N));
}
__device__ __forceinline__ void ldsm_x4(uint32_t r[4], uint32_t addr) {
    asm volatile("ldmatrix.sync.aligned.m8n8.x4.shared.b16 {%0,%1,%2,%3}, [%4];"
                 : "=r"(r[0]), "=r"(r[1]), "=r"(r[2]), "=r"(r[3]) : "r"(addr));
}
__device__ __forceinline__ void mma16816(float d[4], const uint32_t a[4],
                                         const uint32_t b0, const uint32_t b1) {
    asm volatile(
        "mma.sync.aligned.m16n8k16.row.col.f32.bf16.bf16.f32 "
        "{%0,%1,%2,%3}, {%4,%5,%6,%7}, {%8,%9}, {%0,%1,%2,%3};"
        : "+f"(d[0]), "+f"(d[1]), "+f"(d[2]), "+f"(d[3])
        : "r"(a[0]), "r"(a[1]), "r"(a[2]), "r"(a[3]), "r"(b0), "r"(b1));
}
// swizzled byte offset inside a 128-row x 128-byte tile
__device__ __forceinline__ uint32_t swz(int row, int kbyte) {
    return (uint32_t)row * 128 + ((((uint32_t)kbyte >> 4) ^ ((uint32_t)row & 7)) << 4);
}

// ---------------- prep kernels ----------------------------------------------
__global__ void split_f32(const float* __restrict__ in, bf16* __restrict__ o0,
                          bf16* __restrict__ o1) {
    int i = (blockIdx.x * 256 + threadIdx.x) * 4;
    float4 v = *(const float4*)(in + i);
    bf16 h0, l0, h1, l1, h2, l2, h3, l3;
    split2(v.x, h0, l0); split2(v.y, h1, l1);
    split2(v.z, h2, l2); split2(v.w, h3, l3);
    *(uint2*)(o0 + i) = make_uint2(pk(h0, h1), pk(h2, h3));
    *(uint2*)(o1 + i) = make_uint2(pk(l0, l1), pk(l2, l3));
}

__global__ void tsplit_w(const float* __restrict__ Wq, const float* __restrict__ Wk,
                         const float* __restrict__ Wv) {
    __shared__ float t[32][33];
    const float* W = (blockIdx.z == 0) ? Wq : (blockIdx.z == 1) ? Wk : Wv;
    bf16* O0 = (blockIdx.z == 0) ? g_Wq0 : (blockIdx.z == 1) ? g_Wk0 : g_Wv0;
    bf16* O1 = (blockIdx.z == 0) ? g_Wq1 : (blockIdx.z == 1) ? g_Wk1 : g_Wv1;
    int k0 = blockIdx.y * 32, n0 = blockIdx.x * 32;
    int tx = threadIdx.x, ty = threadIdx.y;
#pragma unroll
    for (int i = 0; i < 4; i++)
        t[ty + 8 * i][tx] = W[(size_t)(k0 + ty + 8 * i) * DMODEL + n0 + tx];
    __syncthreads();
#pragma unroll
    for (int i = 0; i < 4; i++) {
        float v = t[tx][ty + 8 * i];           // = W[k0+tx][n0+ty+8i]
        bf16 h, l; split2(v, h, l);
        size_t o = (size_t)(n0 + ty + 8 * i) * DMODEL + k0 + tx;
        O0[o] = h; O1[o] = l;
    }
}

// ---------------- mma.sync GEMM: C[M,N] = sum_k A[m,k] B[n,k], bf16x3 -------
// CTA tile 128x128, K-stage 64, 256 threads = 8 warps in 2x4 (warp tile 64x32).
#define GT 256
#define STG 65536u      // Ah(16K)+Al(16K)+Bh(16K)+Bl(16K), each 128 rows x 128B
#define SMEM_SZ (2u * STG)

__global__ __launch_bounds__(GT, 1)
void gemm_bf16x3(const bf16* __restrict__ A0, const bf16* __restrict__ A1,
                 const bf16* __restrict__ B0, const bf16* __restrict__ B1,
                 int Ktot, int kstart_rb, int tri_skip,
                 float* __restrict__ Cf, bf16* __restrict__ C0, bf16* __restrict__ C1,
                 const float* __restrict__ bias, int bias_mode, int ldc)
{
    const int m0 = blockIdx.y * 128, n0 = blockIdx.x * 128;
    if (tri_skip && (n0 + 128 <= m0)) return;

    extern __shared__ char smem[];
    const uint32_t dataB = s2u(smem);
    const int tid = threadIdx.x;
    const int lane = tid & 31, wid = tid >> 5;
    const int wm = (wid >> 2) * 64;        // warp M offset within tile
    const int wn = (wid & 3) * 32;         // warp N offset within tile

    const int kstart = kstart_rb ? m0 : 0;
    const int S = (Ktot - kstart) >> 6;

    // cp.async mapping: 4 chunks per thread per 16KB tile
    auto issue = [&](int s) {
        const uint32_t st = dataB + (uint32_t)(s & 1) * STG;
        const size_t kbase = (size_t)kstart + ((size_t)s << 6);
#pragma unroll
        for (int t = 0; t < 4; t++) {
            int chunk = tid + t * 256;         // 0..1023
            int row = chunk >> 3, cc = chunk & 7;
            uint32_t so = swz(row, cc << 4);
            size_t go = kbase + (size_t)cc * 8;
            cp16(st + so,         A0 + (size_t)(m0 + row) * Ktot + go);
            cp16(st + 16384 + so, A1 + (size_t)(m0 + row) * Ktot + go);
            cp16(st + 32768 + so, B0 + (size_t)(n0 + row) * Ktot + go);
            cp16(st + 49152 + so, B1 + (size_t)(n0 + row) * Ktot + go);
        }
        cp_commit();
    };

    float acc[4][4][4];
#pragma unroll
    for (int i = 0; i < 4; i++)
#pragma unroll
        for (int j = 0; j < 4; j++)
#pragma unroll
            for (int q = 0; q < 4; q++) acc[i][j][q] = 0.0f;

    issue(0);
    if (S > 1) issue(1); else cp_commit();

    // ldmatrix lane address pieces (constant across stages)
    const int a_r  = (lane & 15);               // row within 16-row chunk
    const int a_kb = (lane >> 4) << 4;          // 0 or 16 bytes (k8 halves)
    const int b_r  = (lane & 7) + ((lane >> 4) << 3);   // row within 16-n chunk
    const int b_kb = ((lane >> 3) & 1) << 4;

    for (int s = 0; s < S; s++) {
        cp_wait<1>();
        __syncthreads();
        const uint32_t st = dataB + (uint32_t)(s & 1) * STG;
        const uint32_t tAh = st, tAl = st + 16384, tBh = st + 32768, tBl = st + 49152;

#pragma unroll
        for (int ks = 0; ks < 4; ks++) {
            const int kb = ks << 5;   // 32 bytes per k16
            uint32_t ah[4][4], al[4][4];
#pragma unroll
            for (int i = 0; i < 4; i++) {
                int r = wm + 16 * i + a_r;
                uint32_t so = swz(r, kb + a_kb);
                ldsm_x4(ah[i], tAh + so);
                ldsm_x4(al[i], tAl + so);
            }
            uint32_t bh[4][2], bl[4][2];
#pragma unroll
            for (int j2 = 0; j2 < 2; j2++) {
                int r = wn + 16 * j2 + b_r;
                uint32_t so = swz(r, kb + b_kb);
                uint32_t t0[4], t1[4];
                ldsm_x4(t0, tBh + so);
                ldsm_x4(t1, tBl + so);
                bh[2*j2][0] = t0[0]; bh[2*j2][1] = t0[1];
                bh[2*j2+1][0] = t0[2]; bh[2*j2+1][1] = t0[3];
                bl[2*j2][0] = t1[0]; bl[2*j2][1] = t1[1];
                bl[2*j2+1][0] = t1[2]; bl[2*j2+1][1] = t1[3];
            }
#pragma unroll
            for (int i = 0; i < 4; i++)
#pragma unroll
                for (int j = 0; j < 4; j++) {
                    mma16816(acc[i][j], ah[i], bh[j][0], bh[j][1]);
                    mma16816(acc[i][j], ah[i], bl[j][0], bl[j][1]);
                    mma16816(acc[i][j], al[i], bh[j][0], bh[j][1]);
                }
        }
        __syncthreads();
        if (s + 2 < S) issue(s + 2); else cp_commit();
    }

    // ---- epilogue ----
    const int rbase = m0 + wm + (lane >> 2);
    const int cbase = n0 + wn + 2 * (lane & 3);
#pragma unroll
    for (int i = 0; i < 4; i++) {
        const int mlo = rbase + 16 * i, mhi = mlo + 8;
        float blo = 0.0f, bhi = 0.0f;
        if (bias_mode == 2) { blo = bias[mlo]; bhi = bias[mhi]; }
#pragma unroll
        for (int j = 0; j < 4; j++) {
            const int c = cbase + 8 * j;
            float d0 = acc[i][j][0], d1 = acc[i][j][1];
            float d2 = acc[i][j][2], d3 = acc[i][j][3];
            if (bias_mode == 1) {
                float b0 = __ldg(bias + c), b1 = __ldg(bias + c + 1);
                d0 += b0; d1 += b1; d2 += b0; d3 += b1;
            } else if (bias_mode == 2) {
                d0 += blo; d1 += blo; d2 += bhi; d3 += bhi;
            }
            if (C0) {
                bf16 h0, l0, h1, l1;
                split2(d0, h0, l0); split2(d1, h1, l1);
                *(uint32_t*)(C0 + (size_t)mlo * ldc + c) = pk(h0, h1);
                *(uint32_t*)(C1 + (size_t)mlo * ldc + c) = pk(l0, l1);
                split2(d2, h0, l0); split2(d3, h1, l1);
                *(uint32_t*)(C0 + (size_t)mhi * ldc + c) = pk(h0, h1);
                *(uint32_t*)(C1 + (size_t)mhi * ldc + c) = pk(l0, l1);
            } else {
                *(float2*)(Cf + (size_t)mlo * ldc + c) = make_float2(d0, d1);
                *(float2*)(Cf + (size_t)mhi * ldc + c) = make_float2(d2, d3);
            }
        }
    }
}

// ---------------- softmax + P split -----------------------------------------
__global__ void softmax_kernel() {
    __shared__ float srow[LSEQ];
    __shared__ float red[8];
    __shared__ float bc;
    const int i = blockIdx.x;
    const float* row = g_S + (size_t)i * LSEQ;
    const int tid = threadIdx.x;
    const float sc = 0.03125f;

    float m = -INFINITY;
    for (int j = i + tid; j < LSEQ; j += 256) { float v = row[j]; srow[j] = v; m = fmaxf(m, v); }
#pragma unroll
    for (int o = 16; o; o >>= 1) m = fmaxf(m, __shfl_xor_sync(~0u, m, o));
    if ((tid & 31) == 0) red[tid >> 5] = m;
    __syncthreads();
    if (tid < 32) {
        float v = (tid < 8) ? red[tid] : -INFINITY;
#pragma unroll
        for (int o = 4; o; o >>= 1) v = fmaxf(v, __shfl_xor_sync(~0u, v, o));
        if (tid == 0) bc = v;
    }
    __syncthreads();
    m = bc;
    __syncthreads();

    float s = 0.0f;
    for (int j = i + tid; j < LSEQ; j += 256) {
        float e = expf((srow[j] - m) * sc);
        srow[j] = e; s += e;
    }
#pragma unroll
    for (int o = 16; o; o >>= 1) s += __shfl_xor_sync(~0u, s, o);
    if ((tid & 31) == 0) red[tid >> 5] = s;
    __syncthreads();
    if (tid < 32) {
        float v = (tid < 8) ? red[tid] : 0.0f;
#pragma unroll
        for (int o = 4; o; o >>= 1) v += __shfl_xor_sync(~0u, v, o);
        if (tid == 0) bc = v;
    }
    __syncthreads();
    const float inv = 1.0f / bc;

    bf16* p0 = g_P0 + (size_t)i * LSEQ;
    bf16* p1 = g_P1 + (size_t)i * LSEQ;
    for (int j = tid; j < LSEQ; j += 256) {
        float v = (j < i) ? 0.0f : srow[j] * inv;
        bf16 h, l; split2(v, h, l);
        p0[j] = h; p1[j] = l;
    }
}

// ---------------- launch -----------------------------------------------------
extern "C" void kernel_launch(void* const* d_in, const int* in_sizes, int n_in,
                              void* d_out, int out_size)
{
    const float* x  = (const float*)d_in[0];
    const float* z  = (const float*)d_in[1];
    const float* Wq = (const float*)d_in[2];
    const float* bq = (const float*)d_in[3];
    const float* Wk = (const float*)d_in[4];
    const float* bk = (const float*)d_in[5];
    const float* Wv = (const float*)d_in[6];
    const float* bv = (const float*)d_in[7];
    float* out = (float*)d_out;

    cudaFuncSetAttribute(gemm_bf16x3, cudaFuncAttributeMaxDynamicSharedMemorySize, SMEM_SZ);

    bf16 *x0, *x1, *z0, *z1, *wq0, *wq1, *wk0, *wk1, *wv0, *wv1;
    bf16 *q0, *q1, *k0, *k1, *vt0, *vt1, *p0, *p1;
    float* S;
    cudaGetSymbolAddress((void**)&x0, g_x0);  cudaGetSymbolAddress((void**)&x1, g_x1);
    cudaGetSymbolAddress((void**)&z0, g_z0);  cudaGetSymbolAddress((void**)&z1, g_z1);
    cudaGetSymbolAddress((void**)&wq0, g_Wq0); cudaGetSymbolAddress((void**)&wq1, g_Wq1);
    cudaGetSymbolAddress((void**)&wk0, g_Wk0); cudaGetSymbolAddress((void**)&wk1, g_Wk1);
    cudaGetSymbolAddress((void**)&wv0, g_Wv0); cudaGetSymbolAddress((void**)&wv1, g_Wv1);
    cudaGetSymbolAddress((void**)&q0, g_Q0);  cudaGetSymbolAddress((void**)&q1, g_Q1);
    cudaGetSymbolAddress((void**)&k0, g_K0);  cudaGetSymbolAddress((void**)&k1, g_K1);
    cudaGetSymbolAddress((void**)&vt0, g_VT0); cudaGetSymbolAddress((void**)&vt1, g_VT1);
    cudaGetSymbolAddress((void**)&p0, g_P0);  cudaGetSymbolAddress((void**)&p1, g_P1);
    cudaGetSymbolAddress((void**)&S, g_S);

    split_f32<<<4096, 256>>>(x, x0, x1);
    split_f32<<<4096, 256>>>(z, z0, z1);
    tsplit_w<<<dim3(32, 32, 3), dim3(32, 8)>>>(Wq, Wk, Wv);

    // Q = x @ Wq + bq
    gemm_bf16x3<<<dim3(8, 32), GT, SMEM_SZ>>>(x0, x1, wq0, wq1, DMODEL, 0, 0,
                                              nullptr, q0, q1, bq, 1, DMODEL);
    // K = z @ Wk + bk
    gemm_bf16x3<<<dim3(8, 32), GT, SMEM_SZ>>>(z0, z1, wk0, wk1, DMODEL, 0, 0,
                                              nullptr, k0, k1, bk, 1, DMODEL);
    // VT[d, l] = (z @ Wv + bv)^T
    gemm_bf16x3<<<dim3(32, 8), GT, SMEM_SZ>>>(wv0, wv1, z0, z1, DMODEL, 0, 0,
                                              nullptr, vt0, vt1, bv, 2, LSEQ);
    // S = Q @ K^T  (triangle skip, fp32 out)
    gemm_bf16x3<<<dim3(32, 32), GT, SMEM_SZ>>>(q0, q1, k0, k1, DMODEL, 0, 1,
                                               S, nullptr, nullptr, nullptr, 0, LSEQ);
    softmax_kernel<<<LSEQ, 256>>>();
    // O = P @ V  (k starts at row-block diagonal)
    gemm_bf16x3<<<dim3(8, 32), GT, SMEM_SZ>>>(p0, p1, vt0, vt1, LSEQ, 1, 0,
                                              out, nullptr, nullptr, nullptr, 0, DMODEL);
}